// round 1
// baseline (speedup 1.0000x reference)
#include <cuda_runtime.h>
#include <math.h>

#define NB 16
#define NC 32
#define NT 13
#define NN 2000
#define NK 20
#define ND (NT*NC)      // 416
#define BT (NB*NT)      // 208
#define SLAB (NN*NC)    // 64000 floats per (b,t)

// ---------------- scratch (device globals; no allocation allowed) ----------------
__device__ float g_xT[NB*NT*NN*NC];      // x transposed to [b,t,n,c]
__device__ float g_h1[NB*NT*NN*NC];      // propagation ping buffer
__device__ float g_left[NB*NN];
__device__ float g_right[NB*NN];
__device__ int   g_idx[NN*NK];
__device__ float g_adj1v[NN*NK];
__device__ float g_Aval[NB*NN*NK];
__device__ float g_sortedR[NB*2048];
__device__ float g_sufHigh[NB*2049];
__device__ float g_cumLowEx[NB*2049];
__device__ float g_u1[ND];
__device__ float g_u2[ND];
__device__ float g_LR0[2];

// ---------------- kernel 1: adj relu + row-normalize + top-K ----------------
__global__ void k_adj(const float* __restrict__ adj) {
    __shared__ float sv[NN];
    __shared__ float rv[256];
    __shared__ int   ri[256];
    __shared__ float sInvDeg;
    int row = blockIdx.x;
    int tid = threadIdx.x;
    const float* arow = adj + (size_t)row * NN;
    float psum = 0.f;
    for (int e = tid; e < NN; e += 256) {
        float v = arow[e];
        v = v > 0.f ? v : 0.f;
        sv[e] = v;
        psum += v;
    }
    rv[tid] = psum;
    __syncthreads();
    for (int s = 128; s > 0; s >>= 1) {
        if (tid < s) rv[tid] += rv[tid + s];
        __syncthreads();
    }
    if (tid == 0) sInvDeg = 1.0f / rv[0];
    __syncthreads();
    float invdeg = sInvDeg;

    for (int it = 0; it < NK; it++) {
        float bv = -1.f; int bi = NN;
        for (int e = tid; e < NN; e += 256) {
            float v = sv[e];
            if (v > bv) { bv = v; bi = e; }
        }
        rv[tid] = bv; ri[tid] = bi;
        __syncthreads();
        for (int s = 128; s > 0; s >>= 1) {
            if (tid < s) {
                float ov = rv[tid + s]; int oi = ri[tid + s];
                if (ov > rv[tid] || (ov == rv[tid] && oi < ri[tid])) {
                    rv[tid] = ov; ri[tid] = oi;
                }
            }
            __syncthreads();
        }
        if (tid == 0) {
            int sel = ri[0];
            g_idx[row * NK + it] = sel;
            g_adj1v[row * NK + it] = rv[0] * invdeg;
            sv[sel] = -2.0f;  // exclude from later iterations
        }
        __syncthreads();
    }
}

// ---------------- kernel 2: u1/u2 = a-slices folded into W2; bias constants ----------------
__global__ void k_u(const float* __restrict__ W2, const float* __restrict__ b2,
                    const float* __restrict__ a) {
    int tid = threadIdx.x;
    if (tid < ND) {
        int t = tid >> 5, c = tid & 31;
        float s1 = 0.f, s2 = 0.f;
        for (int o = 0; o < NC; o++) {
            float w = W2[o * NC + c];
            s1 += a[t * NC + o] * w;
            s2 += a[ND + t * NC + o] * w;
        }
        g_u1[tid] = s1;
        g_u2[tid] = s2;
    } else if (tid == ND) {
        float s = 0.f;
        for (int d = 0; d < ND; d++) s += b2[d & 31] * a[d];
        g_LR0[0] = s;
    } else if (tid == ND + 1) {
        float s = 0.f;
        for (int d = 0; d < ND; d++) s += b2[d & 31] * a[ND + d];
        g_LR0[1] = s;
    }
}

// ---------------- kernel 3: transpose x[b,c,t,n] -> xT[b,t,n,c] ----------------
__global__ void k_tr(const float* __restrict__ x) {
    __shared__ float tile[32][33];
    int bt = blockIdx.y;
    int b = bt / NT, t = bt - b * NT;
    int n0 = blockIdx.x * 32;
    int tx = threadIdx.x, ty = threadIdx.y;
#pragma unroll
    for (int cc = 0; cc < 4; cc++) {
        int c = ty + cc * 8;
        int n = n0 + tx;
        float v = 0.f;
        if (n < NN) v = x[(((size_t)b * NC + c) * NT + t) * NN + n];
        tile[c][tx] = v;
    }
    __syncthreads();
    size_t slab = (size_t)bt * SLAB;
#pragma unroll
    for (int cc = 0; cc < 4; cc++) {
        int nl = ty + cc * 8;
        int n = n0 + nl;
        if (n < NN) g_xT[slab + (size_t)n * NC + tx] = tile[tx][nl];
    }
}

// ---------------- kernel 4: left/right (one warp per (b,n)) ----------------
__global__ void k_lr() {
    int gw = blockIdx.x * 8 + (threadIdx.x >> 5);
    int lane = threadIdx.x & 31;
    if (gw >= NB * NN) return;
    int b = gw / NN, n = gw - b * NN;
    float s1 = 0.f, s2 = 0.f;
#pragma unroll
    for (int t = 0; t < NT; t++) {
        float v = g_xT[((size_t)(b * NT + t) * NN + n) * NC + lane];
        s1 += v * g_u1[t * NC + lane];
        s2 += v * g_u2[t * NC + lane];
    }
#pragma unroll
    for (int o = 16; o > 0; o >>= 1) {
        s1 += __shfl_xor_sync(0xffffffffu, s1, o);
        s2 += __shfl_xor_sync(0xffffffffu, s2, o);
    }
    if (lane == 0) {
        g_left[gw]  = s1 + g_LR0[0];
        g_right[gw] = s2 + g_LR0[1];
    }
}

// ---------------- kernel 5: per-batch sort of right + prefix/suffix exp-sums ----------------
__global__ void k_sort() {
    __shared__ float ss[2048];
    __shared__ float sl[2048];
    __shared__ float sh[2048];
    int b = blockIdx.x;
    int tid = threadIdx.x;

    for (int e = tid; e < 2048; e += 1024)
        ss[e] = (e < NN) ? g_right[b * NN + e] : INFINITY;
    __syncthreads();

    // bitonic sort, ascending
    for (int k2 = 2; k2 <= 2048; k2 <<= 1) {
        for (int j = k2 >> 1; j > 0; j >>= 1) {
            for (int e = tid; e < 2048; e += 1024) {
                int p = e ^ j;
                if (p > e) {
                    bool up = ((e & k2) == 0);
                    float av = ss[e], bvv = ss[p];
                    if ((av > bvv) == up) { ss[e] = bvv; ss[p] = av; }
                }
            }
            __syncthreads();
        }
    }

    // pads (+inf) are at positions >= NN after ascending sort
    for (int e = tid; e < 2048; e += 1024) {
        sl[e] = (e < NN) ? expf(0.2f * ss[e]) : 0.f;
        sh[e] = (e < NN) ? expf(ss[e]) : 0.f;
    }
    __syncthreads();

    // inclusive prefix scan on sl (ascending), inclusive suffix scan on sh
    for (int off = 1; off < 2048; off <<= 1) {
        int e0 = tid, e1 = tid + 1024;
        float l0 = sl[e0] + ((e0 >= off) ? sl[e0 - off] : 0.f);
        float l1 = sl[e1] + ((e1 >= off) ? sl[e1 - off] : 0.f);
        float h0 = sh[e0] + ((e0 + off < 2048) ? sh[e0 + off] : 0.f);
        float h1 = sh[e1] + ((e1 + off < 2048) ? sh[e1 + off] : 0.f);
        __syncthreads();
        sl[e0] = l0; sl[e1] = l1;
        sh[e0] = h0; sh[e1] = h1;
        __syncthreads();
    }

    for (int e = tid; e < 2048; e += 1024) {
        g_sortedR[b * 2048 + e] = ss[e];
        g_cumLowEx[b * 2049 + e + 1] = sl[e];
        g_sufHigh[b * 2049 + e] = sh[e];
    }
    if (tid == 0) {
        g_cumLowEx[b * 2049] = 0.f;
        g_sufHigh[b * 2049 + 2048] = 0.f;
    }
}

// ---------------- kernel 6: A values at the K sparse slots ----------------
__global__ void k_aval() {
    int g = blockIdx.x * blockDim.x + threadIdx.x;
    if (g >= NB * NN) return;
    int b = g / NN, i = g - b * NN;
    float l = g_left[g];
    float theta = -l;
    const float* sr = g_sortedR + b * 2048;
    int lo = 0, hi = 2048;
    while (lo < hi) {
        int mid = (lo + hi) >> 1;
        if (sr[mid] < theta) lo = mid + 1; else hi = mid;
    }
    int pos = lo;  // first index with sorted >= theta  (s>=0 branch)
    float denom = expf(l) * g_sufHigh[b * 2049 + pos]
                + expf(0.2f * l) * g_cumLowEx[b * 2049 + pos];
    float inv = 1.0f / denom;
#pragma unroll
    for (int k = 0; k < NK; k++) {
        int j = g_idx[i * NK + k];
        float s = l + g_right[b * NN + j];
        float num = (s >= 0.f) ? expf(s) : expf(0.2f * s);
        g_Aval[(size_t)g * NK + k] = num * inv + g_adj1v[i * NK + k];
    }
}

// ---------------- kernel 7: propagation step 1 (warp per node, lane = channel) ----------------
__global__ void k_prop1() {
    int bt = blockIdx.y;
    int b = bt / NT;
    int m = blockIdx.x * 8 + (threadIdx.x >> 5);
    int lane = threadIdx.x & 31;
    if (m >= NN) return;
    size_t slab = (size_t)bt * SLAB;
    float own = g_xT[slab + (size_t)m * NC + lane];
    float av = 0.f; int jj = 0;
    if (lane < NK) {
        av = g_Aval[((size_t)b * NN + m) * NK + lane];
        jj = g_idx[m * NK + lane];
    }
    float acc = 0.f;
#pragma unroll
    for (int k = 0; k < NK; k++) {
        int j   = __shfl_sync(0xffffffffu, jj, k);
        float a = __shfl_sync(0xffffffffu, av, k);
        acc += a * g_xT[slab + (size_t)j * NC + lane];
    }
    g_h1[slab + (size_t)m * NC + lane] = 0.05f * own + 0.95f * acc;
}

// ---------------- kernel 8: propagation step 2 fused with W1 projection ----------------
__global__ void k_prop2(float* __restrict__ out, const float* __restrict__ W1,
                        const float* __restrict__ b1) {
    __shared__ float h2s[32][33];
    __shared__ float W1s[NC * NC];
    __shared__ float b1s[NC];
    int tid = threadIdx.x;
    for (int i = tid; i < NC * NC; i += 256) W1s[i] = W1[i];
    if (tid < NC) b1s[tid] = b1[tid];
    int bt = blockIdx.y;
    int b = bt / NT, t = bt - b * NT;
    int n0 = blockIdx.x * 32;
    int w = tid >> 5, lane = tid & 31;
    size_t slab = (size_t)bt * SLAB;

    for (int q = 0; q < 4; q++) {
        int ml = w * 4 + q;
        int m = n0 + ml;
        float val = 0.f;
        if (m < NN) {
            float own = g_xT[slab + (size_t)m * NC + lane];
            float av = 0.f; int jj = 0;
            if (lane < NK) {
                av = g_Aval[((size_t)b * NN + m) * NK + lane];
                jj = g_idx[m * NK + lane];
            }
            float acc = 0.f;
#pragma unroll
            for (int k = 0; k < NK; k++) {
                int j   = __shfl_sync(0xffffffffu, jj, k);
                float a = __shfl_sync(0xffffffffu, av, k);
                acc += a * g_h1[slab + (size_t)j * NC + lane];
            }
            val = 0.05f * own + 0.95f * acc;
        }
        h2s[ml][lane] = val;
    }
    __syncthreads();

#pragma unroll
    for (int q = 0; q < 4; q++) {
        int o = w * 4 + q;
        int n = n0 + lane;
        if (n < NN) {
            float s = b1s[o];
#pragma unroll
            for (int c = 0; c < NC; c++) s += W1s[o * NC + c] * h2s[lane][c];
            out[(((size_t)b * NC + o) * NT + t) * NN + n] = s;
        }
    }
}

// ---------------- launch ----------------
extern "C" void kernel_launch(void* const* d_in, const int* in_sizes, int n_in,
                              void* d_out, int out_size) {
    const float* x   = (const float*)d_in[0];
    const float* adj = (const float*)d_in[1];
    const float* W1  = (const float*)d_in[2];
    const float* b1  = (const float*)d_in[3];
    const float* W2  = (const float*)d_in[4];
    const float* b2  = (const float*)d_in[5];
    const float* a   = (const float*)d_in[6];
    float* out = (float*)d_out;

    k_adj<<<NN, 256>>>(adj);
    k_u<<<1, 512>>>(W2, b2, a);
    {
        dim3 grid(63, BT), block(32, 8);
        k_tr<<<grid, block>>>(x);
    }
    k_lr<<<(NB * NN + 7) / 8, 256>>>();
    k_sort<<<NB, 1024>>>();
    k_aval<<<(NB * NN + 255) / 256, 256>>>();
    {
        dim3 grid(250, BT);
        k_prop1<<<grid, 256>>>();
    }
    {
        dim3 grid(63, BT);
        k_prop2<<<grid, 256>>>(out, W1, b1);
    }
}